// round 14
// baseline (speedup 1.0000x reference)
#include <cuda_runtime.h>
#include <cuda_bf16.h>
#include <math.h>
#include <stdint.h>

// ---------------- problem constants ----------------
#define BATCH 512
#define C1    256
#define H1    20
#define PC    256
#define NR    1152
#define NC    10
#define ND    16

#define NTILES 144           // 18432/128
#define NCHUNK 324           // 4 ic-blocks * 81 taps

// ---------------- scratch ----------------
__device__ uint32_t g_ypk[BATCH * C1 * 400];                    // conv1 out, packed bf16 hi|lo
__device__ __align__(256) unsigned short g_wt[1296 * 8192];     // pre-swizzled W tiles (21.2MB)
__device__ float g_p[BATCH * PC * 36];
__device__ float g_u[BATCH * NR * 8];
__device__ float g_v[BATCH * NC * ND];

// ---------------- helpers ----------------
__device__ __forceinline__ uint32_t smem_u32(const void* p) {
    uint32_t a;
    asm("{ .reg .u64 t; cvta.to.shared.u64 t, %1; cvt.u32.u64 %0, t; }" : "=r"(a) : "l"(p));
    return a;
}
#define SWZ(o) ((o) ^ (((o) >> 3) & 0x70u))

#define CP16(s, g) \
    asm volatile("cp.async.cg.shared.global [%0], [%1], 16;" :: "r"(s), "l"(g))
#define CPC()  asm volatile("cp.async.commit_group;" ::: "memory")
#define CPW1() asm volatile("cp.async.wait_group 1;" ::: "memory")
#define CPW0() asm volatile("cp.async.wait_group 0;" ::: "memory")

#define LDSM4(r, a) \
    asm volatile("ldmatrix.sync.aligned.m8n8.x4.shared.b16 {%0,%1,%2,%3}, [%4];" \
        : "=r"((r)[0]), "=r"((r)[1]), "=r"((r)[2]), "=r"((r)[3]) : "r"(a))

#define MMA16816(d, a, b0, b1) \
    asm volatile("mma.sync.aligned.m16n8k16.row.col.f32.bf16.bf16.f32 " \
        "{%0,%1,%2,%3}, {%4,%5,%6,%7}, {%8,%9}, {%0,%1,%2,%3};" \
        : "+f"((d)[0]), "+f"((d)[1]), "+f"((d)[2]), "+f"((d)[3]) \
        : "r"((a)[0]), "r"((a)[1]), "r"((a)[2]), "r"((a)[3]), "r"(b0), "r"(b1))

__device__ __forceinline__ uint32_t pack_split(float x) {
    __nv_bfloat16 h = __float2bfloat16(x);
    float hf = __bfloat162float(h);
    __nv_bfloat16 l = __float2bfloat16(x - hf);
    return (uint32_t)__bfloat16_as_ushort(h) | ((uint32_t)__bfloat16_as_ushort(l) << 16);
}

// ============================================================
// Kernel 0: split+reorder prim_w into pre-swizzled SW128 tiles
// ============================================================
__global__ __launch_bounds__(256) void wsplit_kernel(const float* __restrict__ w)
{
    unsigned e = blockIdx.x * 256 + threadIdx.x;      // < 5,308,416
    unsigned ic_l = e & 63; unsigned t = e >> 6;
    unsigned oc_l = t & 127; t >>= 7;
    unsigned icc = t & 3; t >>= 2;
    unsigned tap = t % 81; unsigned mt = t / 81;

    float x = w[((size_t)(mt * 128 + oc_l) * 256 + (icc * 64 + ic_l)) * 81 + tap];
    __nv_bfloat16 h = __float2bfloat16(x);
    __nv_bfloat16 l = __float2bfloat16(x - __bfloat162float(h));

    size_t tb = (size_t)(((mt * 81 + tap) * 4 + icc) * 2) * 8192;
    uint32_t off = SWZ(oc_l * 128u + ic_l * 2u) >> 1;
    g_wt[tb + off]        = __bfloat16_as_ushort(h);
    g_wt[tb + 8192 + off] = __bfloat16_as_ushort(l);
}

// ============================================================
// Kernel 1: conv1, register-row-blocked
// ============================================================
__global__ __launch_bounds__(256) void conv1_kernel(
    const float* __restrict__ x, const float* __restrict__ w,
    const float* __restrict__ bias)
{
    __shared__ __align__(16) float xs[28 * 28];
    const int b  = blockIdx.x;
    const int oc = threadIdx.x;

    for (int i = threadIdx.x; i < 196; i += 256)
        *(float4*)(xs + i * 4) = *(const float4*)(x + b * 784 + i * 4);
    __syncthreads();

    float wr[81];
#pragma unroll
    for (int k = 0; k < 81; k++) wr[k] = w[oc * 81 + k];
    const float bv = bias[oc];

    uint32_t* yo = g_ypk + ((size_t)b * C1 + oc) * 400;
    for (int oh = 0; oh < H1; oh++) {
        float acc[20];
#pragma unroll
        for (int ow = 0; ow < 20; ow++) acc[ow] = bv;
#pragma unroll
        for (int kh = 0; kh < 9; kh++) {
            const float* row = xs + (oh + kh) * 28;
            float xr[28];
#pragma unroll
            for (int j = 0; j < 7; j++) {
                float4 v = *(const float4*)(row + j * 4);
                xr[j * 4] = v.x; xr[j * 4 + 1] = v.y;
                xr[j * 4 + 2] = v.z; xr[j * 4 + 3] = v.w;
            }
#pragma unroll
            for (int kw = 0; kw < 9; kw++) {
                const float wv = wr[kh * 9 + kw];
#pragma unroll
                for (int ow = 0; ow < 20; ow++)
                    acc[ow] = fmaf(wv, xr[ow + kw], acc[ow]);
            }
        }
#pragma unroll
        for (int ow = 0; ow < 20; ow++) yo[oh * 20 + ow] = pack_split(acc[ow]);
    }
}

// ============================================================
// Kernel 2: implicit GEMM on mma.sync, split-bf16 (3 terms).
// CTA = 256 oc x 128 n, 512 threads (16 warps 4x4, warp 64x32). grid=144 -> 1 wave.
// (R10-measured configuration, reverted from the 8-warp experiment.)
// ============================================================
#define ST_AH 0
#define ST_AL 32768
#define ST_BH 65536
#define ST_BL 81920
#define ST_STRIDE 98304
#define GEMM_SMEM (1024 + 2 * ST_STRIDE)

__global__ __launch_bounds__(512, 1) void prim_mma_kernel(const float* __restrict__ bias)
{
    extern __shared__ char smem[];
    const uint32_t sb = smem_u32(smem);
    const uint32_t al = (sb + 1023u) & ~1023u;
    const int tid  = threadIdx.x;
    const int lane = tid & 31, wid = tid >> 5;
    const int ntile = blockIdx.x;
    const int wm = wid >> 2, wn = wid & 3;       // 4x4 warps: wm over M(256), wn over N(128)

    // ---- B gather constants: 4 threads per n-row, 16 k-words each ----
    const int nloc = tid & 127;
    const int q    = tid >> 7;                   // 0..3 -> k quarter
    const int n  = ntile * 128 + nloc;
    const int bimg = n / 36, s = n - bimg * 36;
    const int oh = s / 6, ow = s - oh * 6;
    const uint32_t* ybase = g_ypk + (size_t)bimg * C1 * 400 + (oh * 2) * 20 + ow * 2;

    uint32_t rB[16];

    // A stage copy: 8 CP16/thread (Ah rows 0-127 from mt0 tile, 128-255 from mt1)
    auto stage_A = [&](uint32_t dst, int tap, int icc) {
        const char* t0 = (const char*)g_wt + (size_t)((tap) * 4 + icc) * 32768;
        const char* t1 = (const char*)g_wt + (size_t)((81 + tap) * 4 + icc) * 32768;
        CP16(dst + ST_AH + (tid)        * 16, t0 +            (tid)        * 16);
        CP16(dst + ST_AH + (tid + 512)  * 16, t0 +            (tid + 512)  * 16);
        CP16(dst + ST_AH + (tid + 1024) * 16, t1 +            (tid)        * 16);
        CP16(dst + ST_AH + (tid + 1536) * 16, t1 +            (tid + 512)  * 16);
        CP16(dst + ST_AL + (tid)        * 16, t0 + 16384 +    (tid)        * 16);
        CP16(dst + ST_AL + (tid + 512)  * 16, t0 + 16384 +    (tid + 512)  * 16);
        CP16(dst + ST_AL + (tid + 1024) * 16, t1 + 16384 +    (tid)        * 16);
        CP16(dst + ST_AL + (tid + 1536) * 16, t1 + 16384 +    (tid + 512)  * 16);
        CPC();
    };

    // ---- prologue: chunk 0 ----
    {
        const uint32_t* yb = ybase + (size_t)(q * 16) * 400;
#pragma unroll
        for (int i = 0; i < 16; i++) rB[i] = yb[i * 400];
        stage_A(al, 0, 0);
    }

    float acc[4][4][4];
#pragma unroll
    for (int i = 0; i < 4; i++)
#pragma unroll
        for (int j = 0; j < 4; j++)
#pragma unroll
            for (int k = 0; k < 4; k++) acc[i][j][k] = 0.f;

    // ---- ldmatrix lane addressing ----
    const int arow = wm * 64 + (lane & 15);
    const uint32_t a_rbase = (uint32_t)arow * 128;
    const uint32_t a_xor   = (uint32_t)(arow & 7) << 4;
    const uint32_t a_kh    = ((lane >> 4) & 1) * 16;

    const int brow0 = wn * 32 + ((lane >> 4) & 1) * 8 + (lane & 7);
    const uint32_t b_xor = (uint32_t)(brow0 & 7) << 4;
    const uint32_t b_kh  = ((lane >> 3) & 1) * 16;

    for (int c = 0; c < NCHUNK; c++) {
        const uint32_t stg = al + (c & 1) * ST_STRIDE;

        // ---- STS B(c): split hi/lo from packed regs ----
        {
            char* bh = smem + (stg - sb) + ST_BH;
            char* bl = smem + (stg - sb) + ST_BL;
#pragma unroll
            for (int i = 0; i < 16; i += 2) {
                uint32_t hp = __byte_perm(rB[i], rB[i + 1], 0x5410);
                uint32_t lp = __byte_perm(rB[i], rB[i + 1], 0x7632);
                uint32_t off = SWZ((uint32_t)(nloc * 128 + (q * 16 + i) * 2));
                *(uint32_t*)(bh + off) = hp;
                *(uint32_t*)(bl + off) = lp;
            }
        }

        // ---- prefetch chunk c+1 ----
        if (c + 1 < NCHUNK) {
            const int c1 = c + 1;
            const int icc = c1 / 81, tap = c1 - icc * 81;
            const int kh = tap / 9, kw = tap - kh * 9;
            stage_A(al + (c1 & 1) * ST_STRIDE, tap, icc);
            const uint32_t* yb = ybase + (size_t)(icc * 64 + q * 16) * 400 + kh * 20 + kw;
#pragma unroll
            for (int i = 0; i < 16; i++) rB[i] = yb[i * 400];
            CPW1();
        } else {
            CPW0();
        }
        __syncthreads();

        // ---- MMA: 4 k16 steps, 3 split terms (hh, hl, lh) ----
#pragma unroll
        for (int ks = 0; ks < 4; ks++) {
            const uint32_t ak = (uint32_t)(ks * 32) + a_kh;
            const uint32_t bk = (uint32_t)(ks * 32) + b_kh;
            uint32_t bhf[4][2], blf[4][2];
#pragma unroll
            for (int p = 0; p < 2; p++) {
                const uint32_t rb = (uint32_t)(brow0 + p * 16) * 128;
                uint32_t t[4];
                LDSM4(t, stg + ST_BH + rb + (bk ^ b_xor));
                bhf[2 * p][0] = t[0]; bhf[2 * p][1] = t[1];
                bhf[2 * p + 1][0] = t[2]; bhf[2 * p + 1][1] = t[3];
                LDSM4(t, stg + ST_BL + rb + (bk ^ b_xor));
                blf[2 * p][0] = t[0]; blf[2 * p][1] = t[1];
                blf[2 * p + 1][0] = t[2]; blf[2 * p + 1][1] = t[3];
            }
#pragma unroll
            for (int mb = 0; mb < 4; mb++) {
                const uint32_t ra = a_rbase + mb * 2048;
                uint32_t ah[4], alr[4];
                LDSM4(ah,  stg + ST_AH + ra + (ak ^ a_xor));
                LDSM4(alr, stg + ST_AL + ra + (ak ^ a_xor));
#pragma unroll
                for (int nb = 0; nb < 4; nb++) {
                    MMA16816(acc[mb][nb], ah,  bhf[nb][0], bhf[nb][1]);
                    MMA16816(acc[mb][nb], ah,  blf[nb][0], blf[nb][1]);
                    MMA16816(acc[mb][nb], alr, bhf[nb][0], bhf[nb][1]);
                }
            }
        }
        __syncthreads();
    }

    // ---- epilogue: acc + bias -> g_p ----
#pragma unroll
    for (int mb = 0; mb < 4; mb++) {
#pragma unroll
        for (int h = 0; h < 2; h++) {
            const int oc = wm * 64 + mb * 16 + (lane >> 2) + h * 8;
            const float bv = bias[oc];
#pragma unroll
            for (int nb = 0; nb < 4; nb++) {
                const int n0 = ntile * 128 + wn * 32 + nb * 8 + (lane & 3) * 2;
                const int bb = n0 / 36, ss = n0 - bb * 36;
                float2 v;
                v.x = acc[mb][nb][2 * h]     + bv;
                v.y = acc[mb][nb][2 * h + 1] + bv;
                *(float2*)(&g_p[((size_t)bb * PC + oc) * 36 + ss]) = v;
            }
        }
    }
}

// ============================================================
// Kernel 3: reshape + squash -> u (512,1152,8)
// ============================================================
__global__ __launch_bounds__(128) void squash_u_kernel()
{
    const int b = blockIdx.x;
    const int r = blockIdx.y * 128 + threadIdx.x;
    const int m = r / 36, s = r - m * 36;

    float t[8];
    float sn = 0.f;
#pragma unroll
    for (int i = 0; i < 8; i++) {
        t[i] = g_p[((size_t)b * PC + i * 32 + m) * 36 + s];
        sn = fmaf(t[i], t[i], sn);
    }
    const float f = sqrtf(sn) / (1.f + sn);
#pragma unroll
    for (int i = 0; i < 8; i++)
        g_u[((size_t)b * NR + r) * 8 + i] = t[i] * f;
}

// ============================================================
// Kernel 4: fused priors + 3 routing iterations (shuffle reductions,
// iter-0 uniform-softmax shortcut)
// ============================================================
#define PRI_PITCH 17
#define ROUTE_SMEM ((NR * PRI_PITCH + NR + NR) * 4)

__global__ __launch_bounds__(256) void routing_kernel(const float* __restrict__ rw)
{
    extern __shared__ float sm[];
    float* pri   = sm;                       // NR*17
    float* blog  = sm + NR * PRI_PITCH;      // NR
    float* probs = blog + NR;                // NR

    __shared__ float wredA[8];               // max partials
    __shared__ float wredB[8];               // sum partials
    __shared__ float wred2[8 * 16];          // sv partials
    __shared__ float vsh[ND];

    const int b = blockIdx.x, c = blockIdx.y;
    const int tid  = threadIdx.x;
    const int lane = tid & 31, wid = tid >> 5;
    const int o    = tid & 15;
    const int rg   = tid >> 4;

    // ---- priors + iter-0 partial sum (probs uniform when blog==0) ----
    float part = 0.f;
    for (int r = rg; r < NR; r += 16) {
        const float4 u0 = *(const float4*)(g_u + ((size_t)b * NR + r) * 8);
        const float4 u1 = *(const float4*)(g_u + ((size_t)b * NR + r) * 8 + 4);
        const float* wp = rw + (((size_t)c * NR + r) * 8) * 16 + o;
        float a = 0.f;
        a = fmaf(u0.x, wp[0], a);   a = fmaf(u0.y, wp[16], a);
        a = fmaf(u0.z, wp[32], a);  a = fmaf(u0.w, wp[48], a);
        a = fmaf(u1.x, wp[64], a);  a = fmaf(u1.y, wp[80], a);
        a = fmaf(u1.z, wp[96], a);  a = fmaf(u1.w, wp[112], a);
        pri[r * PRI_PITCH + o] = a;
        part += a;
    }
    part += __shfl_xor_sync(0xffffffffu, part, 16);
    if (lane < 16) wred2[wid * 16 + lane] = part;
    __syncthreads();

    float ssum = (float)NR;     // iter-0 unnormalized probs are all 1

    for (int it = 0; it < 3; it++) {
        // (A) finalize sv from wred2, squash -> vsh
        if (tid < 16) {
            float sacc = 0.f;
#pragma unroll
            for (int w = 0; w < 8; w++) sacc += wred2[w * 16 + tid];
            float svv = sacc / ssum;
            float sn = svv * svv;
            sn += __shfl_xor_sync(0x0000ffffu, sn, 1);
            sn += __shfl_xor_sync(0x0000ffffu, sn, 2);
            sn += __shfl_xor_sync(0x0000ffffu, sn, 4);
            sn += __shfl_xor_sync(0x0000ffffu, sn, 8);
            vsh[tid] = svv * sqrtf(sn) / (1.f + sn);
        }
        __syncthreads();
        if (it == 2) break;

        // (B) blog update
        for (int rr = tid; rr < NR; rr += 256) {
            const float* pr = pri + rr * PRI_PITCH;
            float a = 0.f;
#pragma unroll
            for (int oo = 0; oo < ND; oo++) a = fmaf(pr[oo], vsh[oo], a);
            blog[rr] = (it == 0) ? a : (blog[rr] + a);
        }
        __syncthreads();

        // (C) max over blog
        float lm = -3.4e38f;
        for (int rr = tid; rr < NR; rr += 256) lm = fmaxf(lm, blog[rr]);
#pragma unroll
        for (int d = 16; d > 0; d >>= 1)
            lm = fmaxf(lm, __shfl_xor_sync(0xffffffffu, lm, d));
        if (lane == 0) wredA[wid] = lm;
        __syncthreads();
        float mx = wredA[0];
#pragma unroll
        for (int w = 1; w < 8; w++) mx = fmaxf(mx, wredA[w]);

        // (D) exp + sum, store probs
        float ls = 0.f;
        for (int rr = tid; rr < NR; rr += 256) {
            float e = expf(blog[rr] - mx);
            probs[rr] = e;
            ls += e;
        }
#pragma unroll
        for (int d = 16; d > 0; d >>= 1)
            ls += __shfl_xor_sync(0xffffffffu, ls, d);
        if (lane == 0) wredB[wid] = ls;
        __syncthreads();
        ssum = 0.f;
#pragma unroll
        for (int w = 0; w < 8; w++) ssum += wredB[w];

        // (E) sv partials for next iteration
        float p2 = 0.f;
        for (int r = rg; r < NR; r += 16)
            p2 = fmaf(pri[r * PRI_PITCH + o], probs[r], p2);
        p2 += __shfl_xor_sync(0xffffffffu, p2, 16);
        if (lane < 16) wred2[wid * 16 + lane] = p2;
        __syncthreads();
    }

    if (tid < ND) g_v[((size_t)b * NC + c) * ND + tid] = vsh[tid];
}

// ============================================================
// Kernel 5: logits + softmax
// ============================================================
__global__ __launch_bounds__(256) void final_kernel(float* __restrict__ out)
{
    const int b = blockIdx.x * 256 + threadIdx.x;
    if (b >= BATCH) return;

    float lg[NC];
    float mx = -3.4e38f;
#pragma unroll
    for (int c = 0; c < NC; c++) {
        const float* vp = g_v + ((size_t)b * NC + c) * ND;
        float sn = 0.f;
#pragma unroll
        for (int oo = 0; oo < ND; oo++) sn = fmaf(vp[oo], vp[oo], sn);
        lg[c] = sqrtf(sn);
        mx = fmaxf(mx, lg[c]);
    }
    float sum = 0.f;
#pragma unroll
    for (int c = 0; c < NC; c++) { lg[c] = expf(lg[c] - mx); sum += lg[c]; }
    const float inv = 1.f / sum;
#pragma unroll
    for (int c = 0; c < NC; c++) out[b * NC + c] = lg[c] * inv;
}

// ============================================================
extern "C" void kernel_launch(void* const* d_in, const int* in_sizes, int n_in,
                              void* d_out, int out_size)
{
    const float* x       = (const float*)d_in[0];
    const float* conv_w  = (const float*)d_in[1];
    const float* conv_b  = (const float*)d_in[2];
    const float* prim_w  = (const float*)d_in[3];
    const float* prim_b  = (const float*)d_in[4];
    const float* route_w = (const float*)d_in[5];
    float* out = (float*)d_out;

    cudaFuncSetAttribute(prim_mma_kernel,
                         cudaFuncAttributeMaxDynamicSharedMemorySize, GEMM_SMEM);
    cudaFuncSetAttribute(routing_kernel,
                         cudaFuncAttributeMaxDynamicSharedMemorySize, ROUTE_SMEM);

    wsplit_kernel<<<20736, 256>>>(prim_w);
    conv1_kernel<<<BATCH, 256>>>(x, conv_w, conv_b);
    prim_mma_kernel<<<NTILES, 512, GEMM_SMEM>>>(prim_b);
    squash_u_kernel<<<dim3(BATCH, NR / 128), 128>>>();
    routing_kernel<<<dim3(BATCH, NC), 256, ROUTE_SMEM>>>(route_w);
    final_kernel<<<(BATCH + 255) / 256, 256>>>(out);
}

// round 15
// speedup vs baseline: 1.1832x; 1.1832x over previous
#include <cuda_runtime.h>
#include <cuda_bf16.h>
#include <math.h>
#include <stdint.h>

// ---------------- problem constants ----------------
#define BATCH 512
#define C1    256
#define H1    20
#define PC    256
#define NR    1152
#define NC    10
#define ND    16

#define NTILES 144           // 18432/128
#define NCHUNK 324           // 4 ic-blocks * 81 taps

// ---------------- scratch ----------------
// conv1 out, TRANSPOSED: [b][pos(400)][ic(256)] packed bf16 hi|lo (210MB)
__device__ __align__(16) uint32_t g_ypk[BATCH * 400 * 256];
__device__ __align__(256) unsigned short g_wt[1296 * 8192];     // pre-swizzled W tiles (21.2MB)
__device__ float g_p[BATCH * PC * 36];
__device__ float g_u[BATCH * NR * 8];
__device__ float g_v[BATCH * NC * ND];

// ---------------- helpers ----------------
__device__ __forceinline__ uint32_t smem_u32(const void* p) {
    uint32_t a;
    asm("{ .reg .u64 t; cvta.to.shared.u64 t, %1; cvt.u32.u64 %0, t; }" : "=r"(a) : "l"(p));
    return a;
}
#define SWZ(o) ((o) ^ (((o) >> 3) & 0x70u))

#define CP16(s, g) \
    asm volatile("cp.async.cg.shared.global [%0], [%1], 16;" :: "r"(s), "l"(g))
#define CPC()  asm volatile("cp.async.commit_group;" ::: "memory")
#define CPW1() asm volatile("cp.async.wait_group 1;" ::: "memory")
#define CPW0() asm volatile("cp.async.wait_group 0;" ::: "memory")

#define LDSM4(r, a) \
    asm volatile("ldmatrix.sync.aligned.m8n8.x4.shared.b16 {%0,%1,%2,%3}, [%4];" \
        : "=r"((r)[0]), "=r"((r)[1]), "=r"((r)[2]), "=r"((r)[3]) : "r"(a))

#define MMA16816(d, a, b0, b1) \
    asm volatile("mma.sync.aligned.m16n8k16.row.col.f32.bf16.bf16.f32 " \
        "{%0,%1,%2,%3}, {%4,%5,%6,%7}, {%8,%9}, {%0,%1,%2,%3};" \
        : "+f"((d)[0]), "+f"((d)[1]), "+f"((d)[2]), "+f"((d)[3]) \
        : "r"((a)[0]), "r"((a)[1]), "r"((a)[2]), "r"((a)[3]), "r"(b0), "r"(b1))

__device__ __forceinline__ uint32_t pack_split(float x) {
    __nv_bfloat16 h = __float2bfloat16(x);
    float hf = __bfloat162float(h);
    __nv_bfloat16 l = __float2bfloat16(x - hf);
    return (uint32_t)__bfloat16_as_ushort(h) | ((uint32_t)__bfloat16_as_ushort(l) << 16);
}

// ============================================================
// Kernel 0: split+reorder prim_w into pre-swizzled SW128 tiles
// ============================================================
__global__ __launch_bounds__(256) void wsplit_kernel(const float* __restrict__ w)
{
    unsigned e = blockIdx.x * 256 + threadIdx.x;      // < 5,308,416
    unsigned ic_l = e & 63; unsigned t = e >> 6;
    unsigned oc_l = t & 127; t >>= 7;
    unsigned icc = t & 3; t >>= 2;
    unsigned tap = t % 81; unsigned mt = t / 81;

    float x = w[((size_t)(mt * 128 + oc_l) * 256 + (icc * 64 + ic_l)) * 81 + tap];
    __nv_bfloat16 h = __float2bfloat16(x);
    __nv_bfloat16 l = __float2bfloat16(x - __bfloat162float(h));

    size_t tb = (size_t)(((mt * 81 + tap) * 4 + icc) * 2) * 8192;
    uint32_t off = SWZ(oc_l * 128u + ic_l * 2u) >> 1;
    g_wt[tb + off]        = __bfloat16_as_ushort(h);
    g_wt[tb + 8192 + off] = __bfloat16_as_ushort(l);
}

// ============================================================
// Kernel 1: conv1, register-row-blocked; output TRANSPOSED [b][pos][ic]
// (thread = ic -> fully coalesced stores)
// ============================================================
__global__ __launch_bounds__(256) void conv1_kernel(
    const float* __restrict__ x, const float* __restrict__ w,
    const float* __restrict__ bias)
{
    __shared__ __align__(16) float xs[28 * 28];
    const int b  = blockIdx.x;
    const int oc = threadIdx.x;

    for (int i = threadIdx.x; i < 196; i += 256)
        *(float4*)(xs + i * 4) = *(const float4*)(x + b * 784 + i * 4);
    __syncthreads();

    float wr[81];
#pragma unroll
    for (int k = 0; k < 81; k++) wr[k] = w[oc * 81 + k];
    const float bv = bias[oc];

    uint32_t* yo = g_ypk + (size_t)b * 102400 + oc;
    for (int oh = 0; oh < H1; oh++) {
        float acc[20];
#pragma unroll
        for (int ow = 0; ow < 20; ow++) acc[ow] = bv;
#pragma unroll
        for (int kh = 0; kh < 9; kh++) {
            const float* row = xs + (oh + kh) * 28;
            float xr[28];
#pragma unroll
            for (int j = 0; j < 7; j++) {
                float4 v = *(const float4*)(row + j * 4);
                xr[j * 4] = v.x; xr[j * 4 + 1] = v.y;
                xr[j * 4 + 2] = v.z; xr[j * 4 + 3] = v.w;
            }
#pragma unroll
            for (int kw = 0; kw < 9; kw++) {
                const float wv = wr[kh * 9 + kw];
#pragma unroll
                for (int ow = 0; ow < 20; ow++)
                    acc[ow] = fmaf(wv, xr[ow + kw], acc[ow]);
            }
        }
#pragma unroll
        for (int ow = 0; ow < 20; ow++)
            yo[(size_t)(oh * 20 + ow) * 256] = pack_split(acc[ow]);
    }
}

// ============================================================
// Kernel 2: implicit GEMM on mma.sync, split-bf16 (3 terms).
// CTA = 256 oc x 128 n, 512 threads (16 warps 4x4, warp 64x32). grid=144 -> 1 wave.
// B-gather now COALESCED: 4x LDG.128 per thread from transposed y.
// ============================================================
#define ST_AH 0
#define ST_AL 32768
#define ST_BH 65536
#define ST_BL 81920
#define ST_STRIDE 98304
#define GEMM_SMEM (1024 + 2 * ST_STRIDE)

__global__ __launch_bounds__(512, 1) void prim_mma_kernel(const float* __restrict__ bias)
{
    extern __shared__ char smem[];
    const uint32_t sb = smem_u32(smem);
    const uint32_t al = (sb + 1023u) & ~1023u;
    const int tid  = threadIdx.x;
    const int lane = tid & 31, wid = tid >> 5;
    const int ntile = blockIdx.x;
    const int wm = wid >> 2, wn = wid & 3;       // 4x4 warps: wm over M(256), wn over N(128)

    // ---- B gather constants: 4 threads per n-row, 16 contiguous k-words each ----
    const int nloc = tid & 127;
    const int q    = tid >> 7;                   // 0..3 -> k quarter
    const int n  = ntile * 128 + nloc;
    const int bimg = n / 36, s = n - bimg * 36;
    const int oh = s / 6, ow = s - oh * 6;
    // transposed layout: [b][pos][ic]; base at (oh*2, ow*2), + q*16 within ic
    const uint32_t* ybase = g_ypk + (size_t)bimg * 102400 +
                            (size_t)(oh * 40 + ow * 2) * 256 + q * 16;

    uint32_t rB[16];

    auto load_B = [&](int icc, int kh, int kw) {
        const uint4* yb = (const uint4*)(ybase + (size_t)(kh * 20 + kw) * 256 + icc * 64);
        uint4 v0 = yb[0], v1 = yb[1], v2 = yb[2], v3 = yb[3];
        rB[0] = v0.x; rB[1] = v0.y; rB[2]  = v0.z; rB[3]  = v0.w;
        rB[4] = v1.x; rB[5] = v1.y; rB[6]  = v1.z; rB[7]  = v1.w;
        rB[8] = v2.x; rB[9] = v2.y; rB[10] = v2.z; rB[11] = v2.w;
        rB[12] = v3.x; rB[13] = v3.y; rB[14] = v3.z; rB[15] = v3.w;
    };

    // A stage copy: 8 CP16/thread
    auto stage_A = [&](uint32_t dst, int tap, int icc) {
        const char* t0 = (const char*)g_wt + (size_t)((tap) * 4 + icc) * 32768;
        const char* t1 = (const char*)g_wt + (size_t)((81 + tap) * 4 + icc) * 32768;
        CP16(dst + ST_AH + (tid)        * 16, t0 +            (tid)        * 16);
        CP16(dst + ST_AH + (tid + 512)  * 16, t0 +            (tid + 512)  * 16);
        CP16(dst + ST_AH + (tid + 1024) * 16, t1 +            (tid)        * 16);
        CP16(dst + ST_AH + (tid + 1536) * 16, t1 +            (tid + 512)  * 16);
        CP16(dst + ST_AL + (tid)        * 16, t0 + 16384 +    (tid)        * 16);
        CP16(dst + ST_AL + (tid + 512)  * 16, t0 + 16384 +    (tid + 512)  * 16);
        CP16(dst + ST_AL + (tid + 1024) * 16, t1 + 16384 +    (tid)        * 16);
        CP16(dst + ST_AL + (tid + 1536) * 16, t1 + 16384 +    (tid + 512)  * 16);
        CPC();
    };

    // ---- prologue: chunk 0 ----
    load_B(0, 0, 0);
    stage_A(al, 0, 0);

    float acc[4][4][4];
#pragma unroll
    for (int i = 0; i < 4; i++)
#pragma unroll
        for (int j = 0; j < 4; j++)
#pragma unroll
            for (int k = 0; k < 4; k++) acc[i][j][k] = 0.f;

    // ---- ldmatrix lane addressing ----
    const int arow = wm * 64 + (lane & 15);
    const uint32_t a_rbase = (uint32_t)arow * 128;
    const uint32_t a_xor   = (uint32_t)(arow & 7) << 4;
    const uint32_t a_kh    = ((lane >> 4) & 1) * 16;

    const int brow0 = wn * 32 + ((lane >> 4) & 1) * 8 + (lane & 7);
    const uint32_t b_xor = (uint32_t)(brow0 & 7) << 4;
    const uint32_t b_kh  = ((lane >> 3) & 1) * 16;

    for (int c = 0; c < NCHUNK; c++) {
        const uint32_t stg = al + (c & 1) * ST_STRIDE;

        // ---- STS B(c): split hi/lo from packed regs ----
        {
            char* bh = smem + (stg - sb) + ST_BH;
            char* bl = smem + (stg - sb) + ST_BL;
#pragma unroll
            for (int i = 0; i < 16; i += 2) {
                uint32_t hp = __byte_perm(rB[i], rB[i + 1], 0x5410);
                uint32_t lp = __byte_perm(rB[i], rB[i + 1], 0x7632);
                uint32_t off = SWZ((uint32_t)(nloc * 128 + (q * 16 + i) * 2));
                *(uint32_t*)(bh + off) = hp;
                *(uint32_t*)(bl + off) = lp;
            }
        }

        // ---- prefetch chunk c+1 ----
        if (c + 1 < NCHUNK) {
            const int c1 = c + 1;
            const int icc = c1 / 81, tap = c1 - icc * 81;
            const int kh = tap / 9, kw = tap - kh * 9;
            stage_A(al + (c1 & 1) * ST_STRIDE, tap, icc);
            load_B(icc, kh, kw);
            CPW1();
        } else {
            CPW0();
        }
        __syncthreads();

        // ---- MMA: 4 k16 steps, 3 split terms (hh, hl, lh) ----
#pragma unroll
        for (int ks = 0; ks < 4; ks++) {
            const uint32_t ak = (uint32_t)(ks * 32) + a_kh;
            const uint32_t bk = (uint32_t)(ks * 32) + b_kh;
            uint32_t bhf[4][2], blf[4][2];
#pragma unroll
            for (int p = 0; p < 2; p++) {
                const uint32_t rb = (uint32_t)(brow0 + p * 16) * 128;
                uint32_t t[4];
                LDSM4(t, stg + ST_BH + rb + (bk ^ b_xor));
                bhf[2 * p][0] = t[0]; bhf[2 * p][1] = t[1];
                bhf[2 * p + 1][0] = t[2]; bhf[2 * p + 1][1] = t[3];
                LDSM4(t, stg + ST_BL + rb + (bk ^ b_xor));
                blf[2 * p][0] = t[0]; blf[2 * p][1] = t[1];
                blf[2 * p + 1][0] = t[2]; blf[2 * p + 1][1] = t[3];
            }
#pragma unroll
            for (int mb = 0; mb < 4; mb++) {
                const uint32_t ra = a_rbase + mb * 2048;
                uint32_t ah[4], alr[4];
                LDSM4(ah,  stg + ST_AH + ra + (ak ^ a_xor));
                LDSM4(alr, stg + ST_AL + ra + (ak ^ a_xor));
#pragma unroll
                for (int nb = 0; nb < 4; nb++) {
                    MMA16816(acc[mb][nb], ah,  bhf[nb][0], bhf[nb][1]);
                    MMA16816(acc[mb][nb], ah,  blf[nb][0], blf[nb][1]);
                    MMA16816(acc[mb][nb], alr, bhf[nb][0], bhf[nb][1]);
                }
            }
        }
        __syncthreads();
    }

    // ---- epilogue: acc + bias -> g_p ----
#pragma unroll
    for (int mb = 0; mb < 4; mb++) {
#pragma unroll
        for (int h = 0; h < 2; h++) {
            const int oc = wm * 64 + mb * 16 + (lane >> 2) + h * 8;
            const float bv = bias[oc];
#pragma unroll
            for (int nb = 0; nb < 4; nb++) {
                const int n0 = ntile * 128 + wn * 32 + nb * 8 + (lane & 3) * 2;
                const int bb = n0 / 36, ss = n0 - bb * 36;
                float2 v;
                v.x = acc[mb][nb][2 * h]     + bv;
                v.y = acc[mb][nb][2 * h + 1] + bv;
                *(float2*)(&g_p[((size_t)bb * PC + oc) * 36 + ss]) = v;
            }
        }
    }
}

// ============================================================
// Kernel 3: reshape + squash -> u (512,1152,8)
// ============================================================
__global__ __launch_bounds__(128) void squash_u_kernel()
{
    const int b = blockIdx.x;
    const int r = blockIdx.y * 128 + threadIdx.x;
    const int m = r / 36, s = r - m * 36;

    float t[8];
    float sn = 0.f;
#pragma unroll
    for (int i = 0; i < 8; i++) {
        t[i] = g_p[((size_t)b * PC + i * 32 + m) * 36 + s];
        sn = fmaf(t[i], t[i], sn);
    }
    const float f = sqrtf(sn) / (1.f + sn);
#pragma unroll
    for (int i = 0; i < 8; i++)
        g_u[((size_t)b * NR + r) * 8 + i] = t[i] * f;
}

// ============================================================
// Kernel 4: fused priors + 3 routing iterations (R10-measured version)
// ============================================================
#define PRI_PITCH 17
#define ROUTE_SMEM ((NR * PRI_PITCH + NR + NR) * 4)

__global__ __launch_bounds__(256) void routing_kernel(const float* __restrict__ rw)
{
    extern __shared__ float sm[];
    float* pri   = sm;
    float* blog  = sm + NR * PRI_PITCH;
    float* probs = blog + NR;

    __shared__ float redbuf[256];
    __shared__ float sv[ND];
    __shared__ float vsh[ND];

    const int b = blockIdx.x, c = blockIdx.y;
    const int tid = threadIdx.x;
    const int o  = tid & 15;
    const int rg = tid >> 4;

    for (int r = tid; r < NR; r += 256) blog[r] = 0.f;

    for (int r = rg; r < NR; r += 16) {
        const float4 u0 = *(const float4*)(g_u + ((size_t)b * NR + r) * 8);
        const float4 u1 = *(const float4*)(g_u + ((size_t)b * NR + r) * 8 + 4);
        const float* wp = rw + (((size_t)c * NR + r) * 8) * 16 + o;
        float a = 0.f;
        a = fmaf(u0.x, wp[0], a);   a = fmaf(u0.y, wp[16], a);
        a = fmaf(u0.z, wp[32], a);  a = fmaf(u0.w, wp[48], a);
        a = fmaf(u1.x, wp[64], a);  a = fmaf(u1.y, wp[80], a);
        a = fmaf(u1.z, wp[96], a);  a = fmaf(u1.w, wp[112], a);
        pri[r * PRI_PITCH + o] = a;
    }
    __syncthreads();

    for (int it = 0; it < 3; it++) {
        float lm = -3.4e38f;
        for (int r = tid; r < NR; r += 256) lm = fmaxf(lm, blog[r]);
        redbuf[tid] = lm; __syncthreads();
        for (int st = 128; st > 0; st >>= 1) {
            if (tid < st) redbuf[tid] = fmaxf(redbuf[tid], redbuf[tid + st]);
            __syncthreads();
        }
        const float mx = redbuf[0];
        __syncthreads();

        float ls = 0.f;
        for (int r = tid; r < NR; r += 256) {
            float e = expf(blog[r] - mx);
            probs[r] = e;
            ls += e;
        }
        redbuf[tid] = ls; __syncthreads();
        for (int st = 128; st > 0; st >>= 1) {
            if (tid < st) redbuf[tid] += redbuf[tid + st];
            __syncthreads();
        }
        const float ssum = redbuf[0];
        __syncthreads();

        float part = 0.f;
        for (int r = rg; r < NR; r += 16)
            part = fmaf(pri[r * PRI_PITCH + o], probs[r], part);
        redbuf[tid] = part; __syncthreads();
        if (tid < ND) {
            float sum = 0.f;
#pragma unroll
            for (int g = 0; g < 16; g++) sum += redbuf[g * 16 + tid];
            sv[tid] = sum / ssum;
        }
        __syncthreads();
        if (tid < ND) {
            float sn = 0.f;
#pragma unroll
            for (int oo = 0; oo < ND; oo++) sn = fmaf(sv[oo], sv[oo], sn);
            vsh[tid] = sv[tid] * sqrtf(sn) / (1.f + sn);
        }
        __syncthreads();

        if (it < 2) {
            for (int r = tid; r < NR; r += 256) {
                const float* pr = pri + r * PRI_PITCH;
                float a = 0.f;
#pragma unroll
                for (int oo = 0; oo < ND; oo++) a = fmaf(pr[oo], vsh[oo], a);
                blog[r] += a;
            }
            __syncthreads();
        }
    }

    if (tid < ND) g_v[((size_t)b * NC + c) * ND + tid] = vsh[tid];
}

// ============================================================
// Kernel 5: logits + softmax
// ============================================================
__global__ __launch_bounds__(256) void final_kernel(float* __restrict__ out)
{
    const int b = blockIdx.x * 256 + threadIdx.x;
    if (b >= BATCH) return;

    float lg[NC];
    float mx = -3.4e38f;
#pragma unroll
    for (int c = 0; c < NC; c++) {
        const float* vp = g_v + ((size_t)b * NC + c) * ND;
        float sn = 0.f;
#pragma unroll
        for (int oo = 0; oo < ND; oo++) sn = fmaf(vp[oo], vp[oo], sn);
        lg[c] = sqrtf(sn);
        mx = fmaxf(mx, lg[c]);
    }
    float sum = 0.f;
#pragma unroll
    for (int c = 0; c < NC; c++) { lg[c] = expf(lg[c] - mx); sum += lg[c]; }
    const float inv = 1.f / sum;
#pragma unroll
    for (int c = 0; c < NC; c++) out[b * NC + c] = lg[c] * inv;
}

// ============================================================
extern "C" void kernel_launch(void* const* d_in, const int* in_sizes, int n_in,
                              void* d_out, int out_size)
{
    const float* x       = (const float*)d_in[0];
    const float* conv_w  = (const float*)d_in[1];
    const float* conv_b  = (const float*)d_in[2];
    const float* prim_w  = (const float*)d_in[3];
    const float* prim_b  = (const float*)d_in[4];
    const float* route_w = (const float*)d_in[5];
    float* out = (float*)d_out;

    cudaFuncSetAttribute(prim_mma_kernel,
                         cudaFuncAttributeMaxDynamicSharedMemorySize, GEMM_SMEM);
    cudaFuncSetAttribute(routing_kernel,
                         cudaFuncAttributeMaxDynamicSharedMemorySize, ROUTE_SMEM);

    wsplit_kernel<<<20736, 256>>>(prim_w);
    conv1_kernel<<<BATCH, 256>>>(x, conv_w, conv_b);
    prim_mma_kernel<<<NTILES, 512, GEMM_SMEM>>>(prim_b);
    squash_u_kernel<<<dim3(BATCH, NR / 128), 128>>>();
    routing_kernel<<<dim3(BATCH, NC), 256, ROUTE_SMEM>>>(route_w);
    final_kernel<<<(BATCH + 255) / 256, 256>>>(out);
}

// round 17
// speedup vs baseline: 1.2665x; 1.0704x over previous
#include <cuda_runtime.h>
#include <cuda_bf16.h>
#include <math.h>
#include <stdint.h>

// ---------------- problem constants ----------------
#define BATCH 512
#define C1    256
#define H1    20
#define PC    256
#define NR    1152
#define NC    10
#define ND    16

#define NTILES 144           // 18432/128
#define NCHUNK 324           // 4 ic-blocks * 81 taps

// ---------------- scratch ----------------
// conv1 out, TRANSPOSED: [b][pos(400)][ic(256)] packed bf16 hi|lo (210MB)
__device__ __align__(16) uint32_t g_ypk[BATCH * 400 * 256];
__device__ __align__(256) unsigned short g_wt[1296 * 8192];     // pre-swizzled W tiles (21.2MB)
__device__ float g_p[BATCH * PC * 36];
__device__ float g_u[BATCH * NR * 8];
__device__ float g_v[BATCH * NC * ND];

// ---------------- helpers ----------------
__device__ __forceinline__ uint32_t smem_u32(const void* p) {
    uint32_t a;
    asm("{ .reg .u64 t; cvta.to.shared.u64 t, %1; cvt.u32.u64 %0, t; }" : "=r"(a) : "l"(p));
    return a;
}
#define SWZ(o) ((o) ^ (((o) >> 3) & 0x70u))

#define CP16(s, g) \
    asm volatile("cp.async.cg.shared.global [%0], [%1], 16;" :: "r"(s), "l"(g))
#define CPC()  asm volatile("cp.async.commit_group;" ::: "memory")
#define CPW1() asm volatile("cp.async.wait_group 1;" ::: "memory")
#define CPW0() asm volatile("cp.async.wait_group 0;" ::: "memory")

#define LDSM4(r, a) \
    asm volatile("ldmatrix.sync.aligned.m8n8.x4.shared.b16 {%0,%1,%2,%3}, [%4];" \
        : "=r"((r)[0]), "=r"((r)[1]), "=r"((r)[2]), "=r"((r)[3]) : "r"(a))

#define MMA16816(d, a, b0, b1) \
    asm volatile("mma.sync.aligned.m16n8k16.row.col.f32.bf16.bf16.f32 " \
        "{%0,%1,%2,%3}, {%4,%5,%6,%7}, {%8,%9}, {%0,%1,%2,%3};" \
        : "+f"((d)[0]), "+f"((d)[1]), "+f"((d)[2]), "+f"((d)[3]) \
        : "r"((a)[0]), "r"((a)[1]), "r"((a)[2]), "r"((a)[3]), "r"(b0), "r"(b1))

__device__ __forceinline__ uint32_t pack_split(float x) {
    __nv_bfloat16 h = __float2bfloat16(x);
    float hf = __bfloat162float(h);
    __nv_bfloat16 l = __float2bfloat16(x - hf);
    return (uint32_t)__bfloat16_as_ushort(h) | ((uint32_t)__bfloat16_as_ushort(l) << 16);
}

// ============================================================
// Kernel 0: split+reorder prim_w into pre-swizzled SW128 tiles
// ============================================================
__global__ __launch_bounds__(256) void wsplit_kernel(const float* __restrict__ w)
{
    unsigned e = blockIdx.x * 256 + threadIdx.x;      // < 5,308,416
    unsigned ic_l = e & 63; unsigned t = e >> 6;
    unsigned oc_l = t & 127; t >>= 7;
    unsigned icc = t & 3; t >>= 2;
    unsigned tap = t % 81; unsigned mt = t / 81;

    float x = w[((size_t)(mt * 128 + oc_l) * 256 + (icc * 64 + ic_l)) * 81 + tap];
    __nv_bfloat16 h = __float2bfloat16(x);
    __nv_bfloat16 l = __float2bfloat16(x - __bfloat162float(h));

    size_t tb = (size_t)(((mt * 81 + tap) * 4 + icc) * 2) * 8192;
    uint32_t off = SWZ(oc_l * 128u + ic_l * 2u) >> 1;
    g_wt[tb + off]        = __bfloat16_as_ushort(h);
    g_wt[tb + 8192 + off] = __bfloat16_as_ushort(l);
}

// ============================================================
// Kernel 1: conv1, register-row-blocked; output TRANSPOSED [b][pos][ic]
// ============================================================
__global__ __launch_bounds__(256) void conv1_kernel(
    const float* __restrict__ x, const float* __restrict__ w,
    const float* __restrict__ bias)
{
    __shared__ __align__(16) float xs[28 * 28];
    const int b  = blockIdx.x;
    const int oc = threadIdx.x;

    for (int i = threadIdx.x; i < 196; i += 256)
        *(float4*)(xs + i * 4) = *(const float4*)(x + b * 784 + i * 4);
    __syncthreads();

    float wr[81];
#pragma unroll
    for (int k = 0; k < 81; k++) wr[k] = w[oc * 81 + k];
    const float bv = bias[oc];

    uint32_t* yo = g_ypk + (size_t)b * 102400 + oc;
    for (int oh = 0; oh < H1; oh++) {
        float acc[20];
#pragma unroll
        for (int ow = 0; ow < 20; ow++) acc[ow] = bv;
#pragma unroll
        for (int kh = 0; kh < 9; kh++) {
            const float* row = xs + (oh + kh) * 28;
            float xr[28];
#pragma unroll
            for (int j = 0; j < 7; j++) {
                float4 v = *(const float4*)(row + j * 4);
                xr[j * 4] = v.x; xr[j * 4 + 1] = v.y;
                xr[j * 4 + 2] = v.z; xr[j * 4 + 3] = v.w;
            }
#pragma unroll
            for (int kw = 0; kw < 9; kw++) {
                const float wv = wr[kh * 9 + kw];
#pragma unroll
                for (int ow = 0; ow < 20; ow++)
                    acc[ow] = fmaf(wv, xr[ow + kw], acc[ow]);
            }
        }
#pragma unroll
        for (int ow = 0; ow < 20; ow++)
            yo[(size_t)(oh * 20 + ow) * 256] = pack_split(acc[ow]);
    }
}

// ============================================================
// Kernel 2: implicit GEMM on mma.sync, split-bf16 (3 terms).
// CTA = 256 oc x 128 n, 256 threads = 8 warps (4x2), warp tile 64x64.
// grid=144 -> 1 wave. Coalesced B-gather (8x LDG.128/thread, transposed y).
// ============================================================
#define ST_AH 0
#define ST_AL 32768
#define ST_BH 65536
#define ST_BL 81920
#define ST_STRIDE 98304
#define GEMM_SMEM (1024 + 2 * ST_STRIDE)

__global__ __launch_bounds__(256, 1) void prim_mma_kernel(const float* __restrict__ bias)
{
    extern __shared__ char smem[];
    const uint32_t sb = smem_u32(smem);
    const uint32_t al = (sb + 1023u) & ~1023u;
    const int tid  = threadIdx.x;
    const int lane = tid & 31, wid = tid >> 5;
    const int ntile = blockIdx.x;
    const int wm = wid >> 1, wn = wid & 1;       // 4x2 warps: wm over M(256), wn over N(128)

    // ---- B gather constants: 2 threads per n-row, 32 contiguous k-words each ----
    const int nloc = tid & 127;
    const int q    = tid >> 7;                   // 0..1 -> k half
    const int n  = ntile * 128 + nloc;
    const int bimg = n / 36, s = n - bimg * 36;
    const int oh = s / 6, ow = s - oh * 6;
    const uint32_t* ybase = g_ypk + (size_t)bimg * 102400 +
                            (size_t)(oh * 40 + ow * 2) * 256 + q * 32;

    uint32_t rB[32];

    auto load_B = [&](int icc, int kh, int kw) {
        const uint4* yb = (const uint4*)(ybase + (size_t)(kh * 20 + kw) * 256 + icc * 64);
#pragma unroll
        for (int j = 0; j < 8; j++) {
            uint4 v = yb[j];
            rB[j * 4] = v.x; rB[j * 4 + 1] = v.y;
            rB[j * 4 + 2] = v.z; rB[j * 4 + 3] = v.w;
        }
    };

    // A stage: 16 CP16/thread (rows 0-127 from mt0 tile, 128-255 from mt1)
    auto stage_A = [&](uint32_t dst, int tap, int icc) {
        const char* t0 = (const char*)g_wt + (size_t)((tap) * 4 + icc) * 32768;
        const char* t1 = (const char*)g_wt + (size_t)((81 + tap) * 4 + icc) * 32768;
#pragma unroll
        for (int j = 0; j < 4; j++) {
            CP16(dst + ST_AH + (tid + j * 256) * 16,          t0 +         (tid + j * 256) * 16);
            CP16(dst + ST_AH + (1024 + tid + j * 256) * 16,   t1 +         (tid + j * 256) * 16);
            CP16(dst + ST_AL + (tid + j * 256) * 16,          t0 + 16384 + (tid + j * 256) * 16);
            CP16(dst + ST_AL + (1024 + tid + j * 256) * 16,   t1 + 16384 + (tid + j * 256) * 16);
        }
        CPC();
    };

    // ---- prologue: chunk 0 ----
    load_B(0, 0, 0);
    stage_A(al, 0, 0);

    float acc[4][8][4];
#pragma unroll
    for (int i = 0; i < 4; i++)
#pragma unroll
        for (int j = 0; j < 8; j++)
#pragma unroll
            for (int k = 0; k < 4; k++) acc[i][j][k] = 0.f;

    // ---- ldmatrix lane addressing ----
    const int arow = wm * 64 + (lane & 15);
    const uint32_t a_rbase = (uint32_t)arow * 128;
    const uint32_t a_xor   = (uint32_t)(arow & 7) << 4;
    const uint32_t a_kh    = ((lane >> 4) & 1) * 16;

    const int brow0 = wn * 64 + ((lane >> 4) & 1) * 8 + (lane & 7);
    const uint32_t b_xor = (uint32_t)(brow0 & 7) << 4;
    const uint32_t b_kh  = ((lane >> 3) & 1) * 16;

    for (int c = 0; c < NCHUNK; c++) {
        const uint32_t stg = al + (c & 1) * ST_STRIDE;

        // ---- STS B(c): split hi/lo from packed regs ----
        {
            char* bh = smem + (stg - sb) + ST_BH;
            char* bl = smem + (stg - sb) + ST_BL;
#pragma unroll
            for (int i = 0; i < 32; i += 2) {
                uint32_t hp = __byte_perm(rB[i], rB[i + 1], 0x5410);
                uint32_t lp = __byte_perm(rB[i], rB[i + 1], 0x7632);
                uint32_t off = SWZ((uint32_t)(nloc * 128 + (q * 32 + i) * 2));
                *(uint32_t*)(bh + off) = hp;
                *(uint32_t*)(bl + off) = lp;
            }
        }

        // ---- prefetch chunk c+1 ----
        if (c + 1 < NCHUNK) {
            const int c1 = c + 1;
            const int icc = c1 / 81, tap = c1 - icc * 81;
            const int kh = tap / 9, kw = tap - kh * 9;
            stage_A(al + (c1 & 1) * ST_STRIDE, tap, icc);
            load_B(icc, kh, kw);
            CPW1();
        } else {
            CPW0();
        }
        __syncthreads();

        // ---- MMA: 4 k16 steps, 3 split terms (hh, hl, lh) ----
#pragma unroll
        for (int ks = 0; ks < 4; ks++) {
            const uint32_t ak = (uint32_t)(ks * 32) + a_kh;
            const uint32_t bk = (uint32_t)(ks * 32) + b_kh;
            uint32_t bhf[8][2], blf[8][2];
#pragma unroll
            for (int p = 0; p < 4; p++) {
                const uint32_t rb = (uint32_t)(brow0 + p * 16) * 128;
                uint32_t t[4];
                LDSM4(t, stg + ST_BH + rb + (bk ^ b_xor));
                bhf[2 * p][0] = t[0]; bhf[2 * p][1] = t[1];
                bhf[2 * p + 1][0] = t[2]; bhf[2 * p + 1][1] = t[3];
                LDSM4(t, stg + ST_BL + rb + (bk ^ b_xor));
                blf[2 * p][0] = t[0]; blf[2 * p][1] = t[1];
                blf[2 * p + 1][0] = t[2]; blf[2 * p + 1][1] = t[3];
            }
#pragma unroll
            for (int mb = 0; mb < 4; mb++) {
                const uint32_t ra = a_rbase + mb * 2048;
                uint32_t ah[4], alr[4];
                LDSM4(ah,  stg + ST_AH + ra + (ak ^ a_xor));
                LDSM4(alr, stg + ST_AL + ra + (ak ^ a_xor));
#pragma unroll
                for (int nb = 0; nb < 8; nb++) {
                    MMA16816(acc[mb][nb], ah,  bhf[nb][0], bhf[nb][1]);
                    MMA16816(acc[mb][nb], ah,  blf[nb][0], blf[nb][1]);
                    MMA16816(acc[mb][nb], alr, bhf[nb][0], bhf[nb][1]);
                }
            }
        }
        __syncthreads();
    }

    // ---- epilogue: acc + bias -> g_p ----
#pragma unroll
    for (int mb = 0; mb < 4; mb++) {
#pragma unroll
        for (int h = 0; h < 2; h++) {
            const int oc = wm * 64 + mb * 16 + (lane >> 2) + h * 8;
            const float bv = bias[oc];
#pragma unroll
            for (int nb = 0; nb < 8; nb++) {
                const int n0 = ntile * 128 + wn * 64 + nb * 8 + (lane & 3) * 2;
                const int bb = n0 / 36, ss = n0 - bb * 36;
                float2 v;
                v.x = acc[mb][nb][2 * h]     + bv;
                v.y = acc[mb][nb][2 * h + 1] + bv;
                *(float2*)(&g_p[((size_t)bb * PC + oc) * 36 + ss]) = v;
            }
        }
    }
}

// ============================================================
// Kernel 3: reshape + squash -> u (512,1152,8)
// ============================================================
__global__ __launch_bounds__(128) void squash_u_kernel()
{
    const int b = blockIdx.x;
    const int r = blockIdx.y * 128 + threadIdx.x;
    const int m = r / 36, s = r - m * 36;

    float t[8];
    float sn = 0.f;
#pragma unroll
    for (int i = 0; i < 8; i++) {
        t[i] = g_p[((size_t)b * PC + i * 32 + m) * 36 + s];
        sn = fmaf(t[i], t[i], sn);
    }
    const float f = sqrtf(sn) / (1.f + sn);
#pragma unroll
    for (int i = 0; i < 8; i++)
        g_u[((size_t)b * NR + r) * 8 + i] = t[i] * f;
}

// ============================================================
// Kernel 4: fused priors + 3 routing iterations (tree reductions,
// priors phase manually unrolled x2 for MLP)
// ============================================================
#define PRI_PITCH 17
#define ROUTE_SMEM ((NR * PRI_PITCH + NR + NR) * 4)

__global__ __launch_bounds__(256) void routing_kernel(const float* __restrict__ rw)
{
    extern __shared__ float sm[];
    float* pri   = sm;
    float* blog  = sm + NR * PRI_PITCH;
    float* probs = blog + NR;

    __shared__ float redbuf[256];
    __shared__ float sv[ND];
    __shared__ float vsh[ND];

    const int b = blockIdx.x, c = blockIdx.y;
    const int tid = threadIdx.x;
    const int o  = tid & 15;
    const int rg = tid >> 4;

    for (int r = tid; r < NR; r += 256) blog[r] = 0.f;

    // priors: 2 r's per iteration (r, r+16) -> doubled load-level parallelism
    for (int r = rg; r < NR; r += 32) {
        const int r2 = r + 16;
        const float4 u0 = *(const float4*)(g_u + ((size_t)b * NR + r) * 8);
        const float4 u1 = *(const float4*)(g_u + ((size_t)b * NR + r) * 8 + 4);
        const float4 v0 = *(const float4*)(g_u + ((size_t)b * NR + r2) * 8);
        const float4 v1 = *(const float4*)(g_u + ((size_t)b * NR + r2) * 8 + 4);
        const float* wpA = rw + (((size_t)c * NR + r) * 8) * 16 + o;
        const float* wpB = rw + (((size_t)c * NR + r2) * 8) * 16 + o;
        float wa0 = wpA[0],  wa1 = wpA[16], wa2 = wpA[32], wa3 = wpA[48];
        float wa4 = wpA[64], wa5 = wpA[80], wa6 = wpA[96], wa7 = wpA[112];
        float wb0 = wpB[0],  wb1 = wpB[16], wb2 = wpB[32], wb3 = wpB[48];
        float wb4 = wpB[64], wb5 = wpB[80], wb6 = wpB[96], wb7 = wpB[112];
        float a0 = 0.f, a1 = 0.f;
        a0 = fmaf(u0.x, wa0, a0); a0 = fmaf(u0.y, wa1, a0);
        a0 = fmaf(u0.z, wa2, a0); a0 = fmaf(u0.w, wa3, a0);
        a0 = fmaf(u1.x, wa4, a0); a0 = fmaf(u1.y, wa5, a0);
        a0 = fmaf(u1.z, wa6, a0); a0 = fmaf(u1.w, wa7, a0);
        a1 = fmaf(v0.x, wb0, a1); a1 = fmaf(v0.y, wb1, a1);
        a1 = fmaf(v0.z, wb2, a1); a1 = fmaf(v0.w, wb3, a1);
        a1 = fmaf(v1.x, wb4, a1); a1 = fmaf(v1.y, wb5, a1);
        a1 = fmaf(v1.z, wb6, a1); a1 = fmaf(v1.w, wb7, a1);
        pri[r  * PRI_PITCH + o] = a0;
        pri[r2 * PRI_PITCH + o] = a1;
    }
    __syncthreads();

    for (int it = 0; it < 3; it++) {
        float lm = -3.4e38f;
        for (int r = tid; r < NR; r += 256) lm = fmaxf(lm, blog[r]);
        redbuf[tid] = lm; __syncthreads();
        for (int st = 128; st > 0; st >>= 1) {
            if (tid < st) redbuf[tid] = fmaxf(redbuf[tid], redbuf[tid + st]);
            __syncthreads();
        }
        const float mx = redbuf[0];
        __syncthreads();

        float ls = 0.f;
        for (int r = tid; r < NR; r += 256) {
            float e = expf(blog[r] - mx);
            probs[r] = e;
            ls += e;
        }
        redbuf[tid] = ls; __syncthreads();
        for (int st = 128; st > 0; st >>= 1) {
            if (tid < st) redbuf[tid] += redbuf[tid + st];
            __syncthreads();
        }
        const float ssum = redbuf[0];
        __syncthreads();

        float part = 0.f;
        for (int r = rg; r < NR; r += 16)
            part = fmaf(pri[r * PRI_PITCH + o], probs[r], part);
        redbuf[tid] = part; __syncthreads();
        if (tid < ND) {
            float sum = 0.f;
#pragma unroll
            for (int g = 0; g < 16; g++) sum += redbuf[g * 16 + tid];
            sv[tid] = sum / ssum;
        }
        __syncthreads();
        if (tid < ND) {
            float sn = 0.f;
#pragma unroll
            for (int oo = 0; oo < ND; oo++) sn = fmaf(sv[oo], sv[oo], sn);
            vsh[tid] = sv[tid] * sqrtf(sn) / (1.f + sn);
        }
        __syncthreads();

        if (it < 2) {
            for (int r = tid; r < NR; r += 256) {
                const float* pr = pri + r * PRI_PITCH;
                float a = 0.f;
#pragma unroll
                for (int oo = 0; oo < ND; oo++) a = fmaf(pr[oo], vsh[oo], a);
                blog[r] += a;
            }
            __syncthreads();
        }
    }

    if (tid < ND) g_v[((size_t)b * NC + c) * ND + tid] = vsh[tid];
}

// ============================================================
// Kernel 5: logits + softmax
// ============================================================
__global__ __launch_bounds__(256) void final_kernel(float* __restrict__ out)
{
    const int b = blockIdx.x * 256 + threadIdx.x;
    if (b >= BATCH) return;

    float lg[NC];
    float mx = -3.4e38f;
#pragma unroll
    for (int c = 0; c < NC; c++) {
        const float* vp = g_v + ((size_t)b * NC + c) * ND;
        float sn = 0.f;
#pragma unroll
        for (int oo = 0; oo < ND; oo++) sn = fmaf(vp[oo], vp[oo], sn);
        lg[c] = sqrtf(sn);
        mx = fmaxf(mx, lg[c]);
    }
    float sum = 0.f;
#pragma unroll
    for (int c = 0; c < NC; c++) { lg[c] = expf(lg[c] - mx); sum += lg[c]; }
    const float inv = 1.f / sum;
#pragma unroll
    for (int c = 0; c < NC; c++) out[b * NC + c] = lg[c] * inv;
}

// ============================================================
extern "C" void kernel_launch(void* const* d_in, const int* in_sizes, int n_in,
                              void* d_out, int out_size)
{
    const float* x       = (const float*)d_in[0];
    const float* conv_w  = (const float*)d_in[1];
    const float* conv_b  = (const float*)d_in[2];
    const float* prim_w  = (const float*)d_in[3];
    const float* prim_b  = (const float*)d_in[4];
    const float* route_w = (const float*)d_in[5];
    float* out = (float*)d_out;

    cudaFuncSetAttribute(prim_mma_kernel,
                         cudaFuncAttributeMaxDynamicSharedMemorySize, GEMM_SMEM);
    cudaFuncSetAttribute(routing_kernel,
                         cudaFuncAttributeMaxDynamicSharedMemorySize, ROUTE_SMEM);

    wsplit_kernel<<<20736, 256>>>(prim_w);
    conv1_kernel<<<BATCH, 256>>>(x, conv_w, conv_b);
    prim_mma_kernel<<<NTILES, 256, GEMM_SMEM>>>(prim_b);
    squash_u_kernel<<<dim3(BATCH, NR / 128), 128>>>();
    routing_kernel<<<dim3(BATCH, NC), 256, ROUTE_SMEM>>>(route_w);
    final_kernel<<<(BATCH + 255) / 256, 256>>>(out);
}